// round 1
// baseline (speedup 1.0000x reference)
#include <cuda_runtime.h>
#include <math.h>

#define L_  2048
#define B_  8
#define E_  1024
#define Z_  128
#define H_  2048
#define MB_ (L_*B_)   // 16384 rows

// ---------------- scratch (static device allocations; no cudaMalloc) ----------
__device__ float g_ema[MB_*E_];            // 64 MB  silu(ema + x*omega)
__device__ float g_mx [MB_*Z_];            //  8 MB  mx = ema @ Wm^T + bm
__device__ float g_qr [MB_*Z_];            //  8 MB
__device__ float g_kr [MB_*Z_];            //  8 MB
__device__ float g_u  [MB_*E_];            // 64 MB  sigmoid gate
__device__ float g_r  [MB_*H_];            // 128 MB
__device__ float g_v  [MB_*H_];            // 128 MB
__device__ float g_S  [B_*L_*L_];          // 128 MB attn = relu(qk)^2 (masked)
__device__ float g_hr [MB_*H_];            // 128 MB h * r

__device__ __forceinline__ float sigf (float v){ return 1.f/(1.f+expf(-v)); }
__device__ __forceinline__ float siluf(float v){ return v/(1.f+expf(-v)); }

// ---------------- shared GEMM core: 128x128 tile, BK=16, 8x8 per thread ------
struct Tiles { float As[16][132]; float Bs[16][132]; };

// C = A(M,K) * B(N,K)^T   (both row-major; "NT")
__device__ __forceinline__ void gemm_nt(const float* __restrict__ A, int lda,
                                        const float* __restrict__ B, int ldb,
                                        int K, int m0, int n0,
                                        Tiles& s, float (&acc)[8][8])
{
    const int tid = threadIdx.x;
    const int tm = (tid >> 4) << 3;
    const int tn = (tid & 15) << 3;
    for (int k0 = 0; k0 < K; k0 += 16) {
        #pragma unroll
        for (int j = 0; j < 8; j++) {
            int i   = tid + 256*j;
            int row = i >> 4;
            int kk  = i & 15;
            s.As[kk][row] = A[(size_t)(m0+row)*lda + k0 + kk];
            s.Bs[kk][row] = B[(size_t)(n0+row)*ldb + k0 + kk];
        }
        __syncthreads();
        #pragma unroll
        for (int kk = 0; kk < 16; kk++) {
            float a[8], b[8];
            *(float4*)&a[0] = *(const float4*)&s.As[kk][tm];
            *(float4*)&a[4] = *(const float4*)&s.As[kk][tm+4];
            *(float4*)&b[0] = *(const float4*)&s.Bs[kk][tn];
            *(float4*)&b[4] = *(const float4*)&s.Bs[kk][tn+4];
            #pragma unroll
            for (int i = 0; i < 8; i++)
                #pragma unroll
                for (int j = 0; j < 8; j++)
                    acc[i][j] += a[i]*b[j];
        }
        __syncthreads();
    }
}

// C = A(M,K) * B(K,N)   (row-major; "NN"), K loop bounded by Kend
__device__ __forceinline__ void gemm_nn(const float* __restrict__ A, int lda,
                                        const float* __restrict__ B, int ldb,
                                        int Kend, int m0, int n0,
                                        Tiles& s, float (&acc)[8][8])
{
    const int tid = threadIdx.x;
    const int tm = (tid >> 4) << 3;
    const int tn = (tid & 15) << 3;
    for (int k0 = 0; k0 < Kend; k0 += 16) {
        #pragma unroll
        for (int j = 0; j < 8; j++) {
            int i   = tid + 256*j;
            int row = i >> 4;
            int kk  = i & 15;
            s.As[kk][row] = A[(size_t)(m0+row)*lda + k0 + kk];
            int kk2 = i >> 7;
            int nn  = i & 127;
            s.Bs[kk2][nn] = B[(size_t)(k0+kk2)*ldb + n0 + nn];
        }
        __syncthreads();
        #pragma unroll
        for (int kk = 0; kk < 16; kk++) {
            float a[8], b[8];
            *(float4*)&a[0] = *(const float4*)&s.As[kk][tm];
            *(float4*)&a[4] = *(const float4*)&s.As[kk][tm+4];
            *(float4*)&b[0] = *(const float4*)&s.Bs[kk][tn];
            *(float4*)&b[4] = *(const float4*)&s.Bs[kk][tn+4];
            #pragma unroll
            for (int i = 0; i < 8; i++)
                #pragma unroll
                for (int j = 0; j < 8; j++)
                    acc[i][j] += a[i]*b[j];
        }
        __syncthreads();
    }
}

#define ZERO_ACC(acc) { _Pragma("unroll") for (int i=0;i<8;i++) _Pragma("unroll") for (int j=0;j<8;j++) acc[i][j]=0.f; }

// ---------------- kernel 1: EMA linear recurrence + silu(y + x*omega) --------
__global__ void __launch_bounds__(256) k_ema(const float* __restrict__ x,
        const float* __restrict__ delta, const float* __restrict__ alpha,
        const float* __restrict__ ebeta, const float* __restrict__ egam,
        const float* __restrict__ omega)
{
    const int tid = blockIdx.x*256 + threadIdx.x;     // 0..8191 = b*E + e
    const int e   = tid & (E_-1);
    float p0 = sigf(delta[e*2+0]);
    float p1 = sigf(delta[e*2+1]);
    float q0 = 1.f - p0*sigf(alpha[e*2+0]);
    float q1 = 1.f - p1*sigf(alpha[e*2+1]);
    const float sc = 0.70710678118654752f;            // sqrt(1/N), N=2
    float c0 = p0*ebeta[e*2+0]*egam[e*2+0]*sc;
    float c1 = p1*ebeta[e*2+1]*egam[e*2+1]*sc;
    float om = omega[e];
    float h0 = 0.f, h1 = 0.f;
    #pragma unroll 8
    for (int l = 0; l < L_; l++) {
        float xv = x[(size_t)l*(B_*E_) + tid];
        h0 = q0*h0 + xv;
        h1 = q1*h1 + xv;
        float o = c0*h0 + c1*h1 + xv*om;
        g_ema[(size_t)l*(B_*E_) + tid] = siluf(o);
    }
}

// ---------------- kernel 2: mx = ema @ Wm^T + bm ------------------------------
__global__ void __launch_bounds__(256) k_mx(const float* __restrict__ Wm,
                                            const float* __restrict__ bm)
{
    __shared__ Tiles s;
    float acc[8][8]; ZERO_ACC(acc);
    const int m0 = blockIdx.y*128, n0 = blockIdx.x*128;
    gemm_nt(g_ema, E_, Wm, E_, E_, m0, n0, s, acc);
    const int tm = (threadIdx.x >> 4) << 3, tn = (threadIdx.x & 15) << 3;
    #pragma unroll
    for (int i = 0; i < 8; i++)
        #pragma unroll
        for (int j = 0; j < 8; j++) {
            int m = m0+tm+i, n = n0+tn+j;
            g_mx[(size_t)m*Z_ + n] = acc[i][j] + bm[n];
        }
}

// ---------------- kernel 3: z = silu(mx @ Wz^T + bz) -> qr, kr ---------------
__global__ void __launch_bounds__(256) k_z(const float* __restrict__ Wz,
        const float* __restrict__ bz, const float* __restrict__ gamma,
        const float* __restrict__ beta)
{
    __shared__ Tiles s;
    float acc[8][8]; ZERO_ACC(acc);
    const int m0 = blockIdx.y*128;
    gemm_nt(g_mx, Z_, Wz, Z_, Z_, m0, 0, s, acc);
    const int tm = (threadIdx.x >> 4) << 3, tn = (threadIdx.x & 15) << 3;
    #pragma unroll
    for (int i = 0; i < 8; i++)
        #pragma unroll
        for (int j = 0; j < 8; j++) {
            int m = m0+tm+i, n = tn+j;
            float zz = siluf(acc[i][j] + bz[n]);
            g_qr[(size_t)m*Z_ + n] = zz*gamma[n]      + beta[n];
            g_kr[(size_t)m*Z_ + n] = zz*gamma[Z_+n]   + beta[Z_+n];
        }
}

// ---------------- kernel 4: base = x @ Wp^T + bp -> u, r, v ------------------
__global__ void __launch_bounds__(256) k_base(const float* __restrict__ x,
        const float* __restrict__ Wp, const float* __restrict__ bp)
{
    __shared__ Tiles s;
    float acc[8][8]; ZERO_ACC(acc);
    const int m0 = blockIdx.y*128, n0 = blockIdx.x*128;
    gemm_nt(x, E_, Wp, E_, E_, m0, n0, s, acc);
    const int tm = (threadIdx.x >> 4) << 3, tn = (threadIdx.x & 15) << 3;
    #pragma unroll
    for (int i = 0; i < 8; i++)
        #pragma unroll
        for (int j = 0; j < 8; j++) {
            int m = m0+tm+i, n = n0+tn+j;
            float t = acc[i][j] + bp[n];
            if (n < E_) {
                g_u[(size_t)m*E_ + n] = sigf(t);
            } else {
                float sv = siluf(t);
                int n2 = n - E_;
                if (n2 < H_) g_r[(size_t)m*H_ + n2]       = sv;
                else         g_v[(size_t)m*H_ + (n2-H_)]  = sv;
            }
        }
}

// ---------------- kernel 5: S = relu(q k^T / L + bias)^2, causal -------------
__global__ void __launch_bounds__(256) k_S(const float* __restrict__ rpw)
{
    const int b  = blockIdx.z;
    const int m0 = blockIdx.y*128, n0 = blockIdx.x*128;
    if (n0 > m0) return;                       // entirely above diagonal
    __shared__ Tiles s;
    float acc[8][8]; ZERO_ACC(acc);
    gemm_nt(g_qr + b*Z_, B_*Z_, g_kr + b*Z_, B_*Z_, Z_, m0, n0, s, acc);
    float* Sb = g_S + (size_t)b*L_*L_;
    const int tm = (threadIdx.x >> 4) << 3, tn = (threadIdx.x & 15) << 3;
    const float inv = 1.f / (float)L_;
    #pragma unroll
    for (int i = 0; i < 8; i++)
        #pragma unroll
        for (int j = 0; j < 8; j++) {
            int row = m0+tm+i, col = n0+tn+j;
            float v = acc[i][j]*inv + rpw[(L_-1) + col - row];
            v = (col <= row) ? fmaxf(v, 0.f) : 0.f;
            Sb[(size_t)row*L_ + col] = v*v;
        }
}

// ---------------- kernel 6: hr = (S @ v) * r  (causal K truncation) ----------
__global__ void __launch_bounds__(256) k_h()
{
    const int b  = blockIdx.z;
    const int m0 = blockIdx.y*128, n0 = blockIdx.x*128;
    __shared__ Tiles s;
    float acc[8][8]; ZERO_ACC(acc);
    gemm_nn(g_S + (size_t)b*L_*L_, L_, g_v + b*H_, B_*H_, m0+128, m0, n0, s, acc);
    const int tm = (threadIdx.x >> 4) << 3, tn = (threadIdx.x & 15) << 3;
    #pragma unroll
    for (int i = 0; i < 8; i++)
        #pragma unroll
        for (int j = 0; j < 8; j++) {
            int row = m0+tm+i, col = n0+tn+j;      // row=l, col=h
            size_t idx = (size_t)(row*B_ + b)*H_ + col;
            g_hr[idx] = acc[i][j] * g_r[idx];
        }
}

// ---------------- kernel 7: out = x + u*(tanh(hr Whw^T + mx Whu^T + b) - x) --
__global__ void __launch_bounds__(256) k_final(const float* __restrict__ x,
        const float* __restrict__ Whw, const float* __restrict__ bhw,
        const float* __restrict__ Whu, const float* __restrict__ bhu,
        float* __restrict__ out)
{
    __shared__ Tiles s;
    float acc[8][8]; ZERO_ACC(acc);
    const int m0 = blockIdx.y*128, n0 = blockIdx.x*128;
    gemm_nt(g_hr, H_, Whw, H_, H_, m0, n0, s, acc);
    gemm_nt(g_mx, Z_, Whu, Z_, Z_, m0, n0, s, acc);
    const int tm = (threadIdx.x >> 4) << 3, tn = (threadIdx.x & 15) << 3;
    #pragma unroll
    for (int i = 0; i < 8; i++)
        #pragma unroll
        for (int j = 0; j < 8; j++) {
            int m = m0+tm+i, n = n0+tn+j;
            float t  = acc[i][j] + bhw[n] + bhu[n];
            float hh = tanhf(t);
            size_t idx = (size_t)m*E_ + n;
            float xv = x[idx];
            out[idx] = xv + g_u[idx]*(hh - xv);
        }
}

// -----------------------------------------------------------------------------
extern "C" void kernel_launch(void* const* d_in, const int* in_sizes, int n_in,
                              void* d_out, int out_size)
{
    const float* x     = (const float*)d_in[0];
    // d_in[1] = attn_mask (unused; causality handled analytically)
    const float* delta = (const float*)d_in[2];
    const float* alpha = (const float*)d_in[3];
    const float* ebeta = (const float*)d_in[4];
    const float* egam  = (const float*)d_in[5];
    const float* omega = (const float*)d_in[6];
    const float* Wm    = (const float*)d_in[7];
    const float* bm    = (const float*)d_in[8];
    const float* Wz    = (const float*)d_in[9];
    const float* bz    = (const float*)d_in[10];
    const float* Wp    = (const float*)d_in[11];
    const float* bp    = (const float*)d_in[12];
    const float* Whw   = (const float*)d_in[13];
    const float* bhw   = (const float*)d_in[14];
    const float* Whu   = (const float*)d_in[15];
    const float* bhu   = (const float*)d_in[16];
    const float* gamma = (const float*)d_in[17];
    const float* beta  = (const float*)d_in[18];
    const float* rpw   = (const float*)d_in[19];
    float* out = (float*)d_out;

    k_ema  <<<32, 256>>>(x, delta, alpha, ebeta, egam, omega);
    k_mx   <<<dim3(1, 128), 256>>>(Wm, bm);
    k_z    <<<dim3(1, 128), 256>>>(Wz, bz, gamma, beta);
    k_base <<<dim3(40, 128), 256>>>(x, Wp, bp);
    k_S    <<<dim3(16, 16, 8), 256>>>(rpw);
    k_h    <<<dim3(16, 16, 8), 256>>>();
    k_final<<<dim3(8, 128), 256>>>(x, Whw, bhw, Whu, bhu, out);
}

// round 2
// speedup vs baseline: 2.7934x; 2.7934x over previous
#include <cuda_runtime.h>
#include <math.h>
#include <stdint.h>

#define L_  2048
#define B_  8
#define E_  1024
#define Z_  128
#define H_  2048
#define MB_ (L_*B_)   // 16384 rows
#define CH_ 16        // ema chunks
#define CL_ (L_/CH_)  // 128 steps per chunk

// ---------------- scratch (static device allocations; no cudaMalloc) ----------
__device__ float g_ema[MB_*E_];            // 64 MB
__device__ float g_mx [MB_*Z_];            //  8 MB
__device__ float g_qr [MB_*Z_];            //  8 MB
__device__ float g_kr [MB_*Z_];            //  8 MB
__device__ float g_u  [MB_*E_];            // 64 MB
__device__ float g_r  [MB_*H_];            // 128 MB
__device__ float g_v  [MB_*H_];            // 128 MB
__device__ float g_S  [B_*L_*L_];          // 128 MB
__device__ float g_hr [MB_*H_];            // 128 MB
__device__ float g_hend[2*CH_*B_*E_];      // ema chunk end states
__device__ float g_cin [2*CH_*B_*E_];      // ema chunk carry-in

__device__ __forceinline__ float sigf (float v){ return 1.f/(1.f+expf(-v)); }
__device__ __forceinline__ float siluf(float v){ return v/(1.f+expf(-v)); }
__device__ __forceinline__ float tf32r(float x){
    uint32_t u; asm("cvt.rna.tf32.f32 %0, %1;" : "=r"(u) : "f"(x));
    return __uint_as_float(u);
}

// ---------------- tf32 mma core -----------------------------------------------
// block tile 128x128, BK=16, 8 warps in 4x2 grid, warp tile 32x64
// acc[mt][nt][4]: mt in {0,1} (16-row tiles), nt in {0..7} (8-col tiles)

struct SMem {
    float A[128][20];
    union { float Bnt[128][20]; float Bnn[16][136]; };
};

__device__ __forceinline__ void mma8(float (&c)[4], const uint32_t (&a)[4], const uint32_t (&b)[2]) {
    asm volatile(
        "mma.sync.aligned.m16n8k8.row.col.f32.tf32.tf32.f32 "
        "{%0,%1,%2,%3},{%4,%5,%6,%7},{%8,%9},{%0,%1,%2,%3};\n"
        : "+f"(c[0]), "+f"(c[1]), "+f"(c[2]), "+f"(c[3])
        : "r"(a[0]), "r"(a[1]), "r"(a[2]), "r"(a[3]), "r"(b[0]), "r"(b[1]));
}

__device__ __forceinline__ void load_A128(SMem& s, const float* __restrict__ A,
                                          int lda, int m0, int k0, int tid) {
    #pragma unroll
    for (int it = 0; it < 2; it++) {
        int i = tid + 256*it;
        int row = i >> 2, v4 = (i & 3) << 2;
        float4 f = *(const float4*)(A + (size_t)(m0+row)*lda + k0 + v4);
        float4 o = make_float4(tf32r(f.x), tf32r(f.y), tf32r(f.z), tf32r(f.w));
        *(float4*)&s.A[row][v4] = o;
    }
}
__device__ __forceinline__ void load_Bnt(SMem& s, const float* __restrict__ B,
                                         int ldb, int n0, int k0, int tid) {
    #pragma unroll
    for (int it = 0; it < 2; it++) {
        int i = tid + 256*it;
        int row = i >> 2, v4 = (i & 3) << 2;
        float4 f = *(const float4*)(B + (size_t)(n0+row)*ldb + k0 + v4);
        float4 o = make_float4(tf32r(f.x), tf32r(f.y), tf32r(f.z), tf32r(f.w));
        *(float4*)&s.Bnt[row][v4] = o;
    }
}
__device__ __forceinline__ void load_Bnn(SMem& s, const float* __restrict__ B,
                                         int ldb, int n0, int k0, int tid) {
    #pragma unroll
    for (int it = 0; it < 2; it++) {
        int i = tid + 256*it;
        int kk = i >> 5, n4 = (i & 31) << 2;
        float4 f = *(const float4*)(B + (size_t)(k0+kk)*ldb + n0 + n4);
        float4 o = make_float4(tf32r(f.x), tf32r(f.y), tf32r(f.z), tf32r(f.w));
        *(float4*)&s.Bnn[kk][n4] = o;
    }
}

__device__ __forceinline__ void mma_step_nt(SMem& s, float (&acc)[2][8][4],
                                            int wm, int wn, int g, int t) {
    #pragma unroll
    for (int k8 = 0; k8 < 16; k8 += 8) {
        uint32_t a[2][4];
        #pragma unroll
        for (int mt = 0; mt < 2; mt++) {
            int r = wm + mt*16 + g;
            a[mt][0] = __float_as_uint(s.A[r  ][k8+t  ]);
            a[mt][1] = __float_as_uint(s.A[r+8][k8+t  ]);
            a[mt][2] = __float_as_uint(s.A[r  ][k8+t+4]);
            a[mt][3] = __float_as_uint(s.A[r+8][k8+t+4]);
        }
        #pragma unroll
        for (int nt = 0; nt < 8; nt++) {
            int cN = wn + nt*8 + g;
            uint32_t b[2];
            b[0] = __float_as_uint(s.Bnt[cN][k8+t  ]);
            b[1] = __float_as_uint(s.Bnt[cN][k8+t+4]);
            #pragma unroll
            for (int mt = 0; mt < 2; mt++) mma8(acc[mt][nt], a[mt], b);
        }
    }
}
__device__ __forceinline__ void mma_step_nn(SMem& s, float (&acc)[2][8][4],
                                            int wm, int wn, int g, int t) {
    #pragma unroll
    for (int k8 = 0; k8 < 16; k8 += 8) {
        uint32_t a[2][4];
        #pragma unroll
        for (int mt = 0; mt < 2; mt++) {
            int r = wm + mt*16 + g;
            a[mt][0] = __float_as_uint(s.A[r  ][k8+t  ]);
            a[mt][1] = __float_as_uint(s.A[r+8][k8+t  ]);
            a[mt][2] = __float_as_uint(s.A[r  ][k8+t+4]);
            a[mt][3] = __float_as_uint(s.A[r+8][k8+t+4]);
        }
        #pragma unroll
        for (int nt = 0; nt < 8; nt++) {
            int cN = wn + nt*8 + g;
            uint32_t b[2];
            b[0] = __float_as_uint(s.Bnn[k8+t  ][cN]);
            b[1] = __float_as_uint(s.Bnn[k8+t+4][cN]);
            #pragma unroll
            for (int mt = 0; mt < 2; mt++) mma8(acc[mt][nt], a[mt], b);
        }
    }
}

// C += A(M,K) * B(N,K)^T
__device__ __forceinline__ void gemm_nt_mma(const float* __restrict__ A, int lda,
                                            const float* __restrict__ B, int ldb,
                                            int K, int m0, int n0,
                                            SMem& s, float (&acc)[2][8][4]) {
    const int tid = threadIdx.x;
    const int wid = tid >> 5, lane = tid & 31;
    const int wm = (wid >> 1) * 32, wn = (wid & 1) * 64;
    const int g = lane >> 2, t = lane & 3;
    for (int k0 = 0; k0 < K; k0 += 16) {
        load_A128(s, A, lda, m0, k0, tid);
        load_Bnt (s, B, ldb, n0, k0, tid);
        __syncthreads();
        mma_step_nt(s, acc, wm, wn, g, t);
        __syncthreads();
    }
}
// C += A(M,K) * B(K,N)
__device__ __forceinline__ void gemm_nn_mma(const float* __restrict__ A, int lda,
                                            const float* __restrict__ B, int ldb,
                                            int K, int m0, int n0,
                                            SMem& s, float (&acc)[2][8][4]) {
    const int tid = threadIdx.x;
    const int wid = tid >> 5, lane = tid & 31;
    const int wm = (wid >> 1) * 32, wn = (wid & 1) * 64;
    const int g = lane >> 2, t = lane & 3;
    for (int k0 = 0; k0 < K; k0 += 16) {
        load_A128(s, A, lda, m0, k0, tid);
        load_Bnn (s, B, ldb, n0, k0, tid);
        __syncthreads();
        mma_step_nn(s, acc, wm, wn, g, t);
        __syncthreads();
    }
}

#define ZERO_ACC4(acc) { _Pragma("unroll") for (int i=0;i<2;i++) _Pragma("unroll") for (int j=0;j<8;j++) _Pragma("unroll") for (int q=0;q<4;q++) acc[i][j][q]=0.f; }

// epilogue iteration: gives (row, col, value) per accumulator element
#define EPI_BEGIN \
    { const int wid_ = threadIdx.x >> 5, lane_ = threadIdx.x & 31; \
      const int wm_ = (wid_ >> 1)*32, wn_ = (wid_ & 1)*64; \
      const int g_ = lane_ >> 2, t_ = lane_ & 3; \
      _Pragma("unroll") for (int mt = 0; mt < 2; mt++) \
      _Pragma("unroll") for (int nt = 0; nt < 8; nt++) \
      _Pragma("unroll") for (int q = 0; q < 4; q++) { \
          int row = m0 + wm_ + mt*16 + g_ + ((q >= 2) ? 8 : 0); \
          int col = n0 + wn_ + nt*8 + 2*t_ + (q & 1); \
          float vv = acc[mt][nt][q];
#define EPI_END } }

// ---------------- EMA: 3-phase chunked linear scan ----------------------------
__device__ __forceinline__ void ema_params(int e, const float* delta, const float* alpha,
        float& q0, float& q1) {
    float p0 = sigf(delta[e*2+0]);
    float p1 = sigf(delta[e*2+1]);
    q0 = 1.f - p0*sigf(alpha[e*2+0]);
    q1 = 1.f - p1*sigf(alpha[e*2+1]);
}

__global__ void __launch_bounds__(256) k_ema_a(const float* __restrict__ x,
        const float* __restrict__ delta, const float* __restrict__ alpha)
{
    const int gt = blockIdx.x*256 + threadIdx.x;   // 0 .. CH_*8192-1
    const int be = gt & (B_*E_-1);
    const int c  = gt >> 13;
    const int e  = be & (E_-1);
    float q0, q1; ema_params(e, delta, alpha, q0, q1);
    float h0 = 0.f, h1 = 0.f;
    const float* xp = x + (size_t)(c*CL_)*(B_*E_) + be;
    #pragma unroll 4
    for (int l = 0; l < CL_; l++) {
        float xv = xp[(size_t)l*(B_*E_)];
        h0 = q0*h0 + xv;
        h1 = q1*h1 + xv;
    }
    g_hend[(size_t)c*(B_*E_) + be]                 = h0;
    g_hend[(size_t)(CH_+c)*(B_*E_) + be]           = h1;
}

__global__ void __launch_bounds__(256) k_ema_b(const float* __restrict__ delta,
        const float* __restrict__ alpha)
{
    const int be = blockIdx.x*256 + threadIdx.x;   // 0..8191
    const int e  = be & (E_-1);
    float q0, q1; ema_params(e, delta, alpha, q0, q1);
    float qp0 = q0, qp1 = q1;
    #pragma unroll
    for (int i = 0; i < 7; i++) { qp0 *= qp0; qp1 *= qp1; }   // q^128
    float c0 = 0.f, c1 = 0.f;
    for (int c = 0; c < CH_; c++) {
        g_cin[(size_t)c*(B_*E_) + be]        = c0;
        g_cin[(size_t)(CH_+c)*(B_*E_) + be]  = c1;
        c0 = qp0*c0 + g_hend[(size_t)c*(B_*E_) + be];
        c1 = qp1*c1 + g_hend[(size_t)(CH_+c)*(B_*E_) + be];
    }
}

__global__ void __launch_bounds__(256) k_ema_c(const float* __restrict__ x,
        const float* __restrict__ delta, const float* __restrict__ alpha,
        const float* __restrict__ ebeta, const float* __restrict__ egam,
        const float* __restrict__ omega)
{
    const int gt = blockIdx.x*256 + threadIdx.x;
    const int be = gt & (B_*E_-1);
    const int c  = gt >> 13;
    const int e  = be & (E_-1);
    float p0 = sigf(delta[e*2+0]);
    float p1 = sigf(delta[e*2+1]);
    float q0 = 1.f - p0*sigf(alpha[e*2+0]);
    float q1 = 1.f - p1*sigf(alpha[e*2+1]);
    const float sc = 0.70710678118654752f;
    float c0 = p0*ebeta[e*2+0]*egam[e*2+0]*sc;
    float c1 = p1*ebeta[e*2+1]*egam[e*2+1]*sc;
    float om = omega[e];
    float h0 = g_cin[(size_t)c*(B_*E_) + be];
    float h1 = g_cin[(size_t)(CH_+c)*(B_*E_) + be];
    const size_t base = (size_t)(c*CL_)*(B_*E_) + be;
    #pragma unroll 4
    for (int l = 0; l < CL_; l++) {
        float xv = x[base + (size_t)l*(B_*E_)];
        h0 = q0*h0 + xv;
        h1 = q1*h1 + xv;
        float o = c0*h0 + c1*h1 + xv*om;
        g_ema[base + (size_t)l*(B_*E_)] = siluf(o);
    }
}

// ---------------- kernel 2: mx = ema @ Wm^T + bm ------------------------------
__global__ void __launch_bounds__(256) k_mx(const float* __restrict__ Wm,
                                            const float* __restrict__ bm)
{
    __shared__ SMem s;
    float acc[2][8][4]; ZERO_ACC4(acc);
    const int m0 = blockIdx.y*128, n0 = blockIdx.x*128;
    gemm_nt_mma(g_ema, E_, Wm, E_, E_, m0, n0, s, acc);
    EPI_BEGIN
        g_mx[(size_t)row*Z_ + col] = vv + bm[col];
    EPI_END
}

// ---------------- kernel 3: z (fp32 FFMA for precision; tiny) -----------------
struct TilesF { float As[16][132]; float Bs[16][132]; };
__global__ void __launch_bounds__(256) k_z(const float* __restrict__ Wz,
        const float* __restrict__ bz, const float* __restrict__ gamma,
        const float* __restrict__ beta)
{
    __shared__ TilesF s;
    float acc[8][8];
    #pragma unroll
    for (int i=0;i<8;i++)
        #pragma unroll
        for (int j=0;j<8;j++) acc[i][j]=0.f;
    const int m0 = blockIdx.y*128;
    const int tid = threadIdx.x;
    const int tm = (tid >> 4) << 3, tn = (tid & 15) << 3;
    for (int k0 = 0; k0 < Z_; k0 += 16) {
        #pragma unroll
        for (int j = 0; j < 8; j++) {
            int i = tid + 256*j;
            int row = i >> 4, kk = i & 15;
            s.As[kk][row] = g_mx[(size_t)(m0+row)*Z_ + k0 + kk];
            s.Bs[kk][row] = Wz[(size_t)row*Z_ + k0 + kk];
        }
        __syncthreads();
        #pragma unroll
        for (int kk = 0; kk < 16; kk++) {
            float a[8], b[8];
            *(float4*)&a[0] = *(const float4*)&s.As[kk][tm];
            *(float4*)&a[4] = *(const float4*)&s.As[kk][tm+4];
            *(float4*)&b[0] = *(const float4*)&s.Bs[kk][tn];
            *(float4*)&b[4] = *(const float4*)&s.Bs[kk][tn+4];
            #pragma unroll
            for (int i = 0; i < 8; i++)
                #pragma unroll
                for (int j = 0; j < 8; j++)
                    acc[i][j] += a[i]*b[j];
        }
        __syncthreads();
    }
    #pragma unroll
    for (int i = 0; i < 8; i++)
        #pragma unroll
        for (int j = 0; j < 8; j++) {
            int m = m0+tm+i, n = tn+j;
            float zz = siluf(acc[i][j] + bz[n]);
            g_qr[(size_t)m*Z_ + n] = zz*gamma[n]    + beta[n];
            g_kr[(size_t)m*Z_ + n] = zz*gamma[Z_+n] + beta[Z_+n];
        }
}

// ---------------- kernel 4: base = x @ Wp^T + bp -> u, r, v ------------------
__global__ void __launch_bounds__(256) k_base(const float* __restrict__ x,
        const float* __restrict__ Wp, const float* __restrict__ bp)
{
    __shared__ SMem s;
    float acc[2][8][4]; ZERO_ACC4(acc);
    const int m0 = blockIdx.y*128, n0 = blockIdx.x*128;
    gemm_nt_mma(x, E_, Wp, E_, E_, m0, n0, s, acc);
    EPI_BEGIN
        float tv = vv + bp[col];
        if (col < E_) {
            g_u[(size_t)row*E_ + col] = sigf(tv);
        } else {
            float sv = siluf(tv);
            int n2 = col - E_;
            if (n2 < H_) g_r[(size_t)row*H_ + n2]      = sv;
            else         g_v[(size_t)row*H_ + (n2-H_)] = sv;
        }
    EPI_END
}

// ---------------- kernel 5: S = relu(q k^T / L + bias)^2, causal -------------
__global__ void __launch_bounds__(256) k_S(const float* __restrict__ rpw)
{
    const int b  = blockIdx.z;
    const int m0 = blockIdx.y*128, n0 = blockIdx.x*128;
    if (n0 > m0) return;
    __shared__ SMem s;
    float acc[2][8][4]; ZERO_ACC4(acc);
    gemm_nt_mma(g_qr + b*Z_, B_*Z_, g_kr + b*Z_, B_*Z_, Z_, m0, n0, s, acc);
    float* Sb = g_S + (size_t)b*L_*L_;
    const float inv = 1.f / (float)L_;
    EPI_BEGIN
        float v = vv*inv + rpw[(L_-1) + col - row];
        v = (col <= row) ? fmaxf(v, 0.f) : 0.f;
        Sb[(size_t)row*L_ + col] = v*v;
    EPI_END
}

// ---------------- kernel 6: hr = (S @ v) * r  (causal K truncation) ----------
__global__ void __launch_bounds__(256) k_h()
{
    const int b  = blockIdx.z;
    const int m0 = blockIdx.y*128, n0 = blockIdx.x*128;
    __shared__ SMem s;
    float acc[2][8][4]; ZERO_ACC4(acc);
    gemm_nn_mma(g_S + (size_t)b*L_*L_, L_, g_v + b*H_, B_*H_, m0+128, m0, n0, s, acc);
    EPI_BEGIN
        size_t idx = (size_t)(row*B_ + b)*H_ + col;
        g_hr[idx] = vv * g_r[idx];
    EPI_END
}

// ---------------- kernel 7: out = x + u*(tanh(hr Whw^T + mx Whu^T + b) - x) --
__global__ void __launch_bounds__(256) k_final(const float* __restrict__ x,
        const float* __restrict__ Whw, const float* __restrict__ bhw,
        const float* __restrict__ Whu, const float* __restrict__ bhu,
        float* __restrict__ out)
{
    __shared__ SMem s;
    float acc[2][8][4]; ZERO_ACC4(acc);
    const int m0 = blockIdx.y*128, n0 = blockIdx.x*128;
    gemm_nt_mma(g_hr, H_, Whw, H_, H_, m0, n0, s, acc);
    gemm_nt_mma(g_mx, Z_, Whu, Z_, Z_, m0, n0, s, acc);
    EPI_BEGIN
        float tv  = vv + bhw[col] + bhu[col];
        float hh  = tanhf(tv);
        size_t idx = (size_t)row*E_ + col;
        float xv = x[idx];
        out[idx] = xv + g_u[idx]*(hh - xv);
    EPI_END
}

// -----------------------------------------------------------------------------
extern "C" void kernel_launch(void* const* d_in, const int* in_sizes, int n_in,
                              void* d_out, int out_size)
{
    const float* x     = (const float*)d_in[0];
    const float* delta = (const float*)d_in[2];
    const float* alpha = (const float*)d_in[3];
    const float* ebeta = (const float*)d_in[4];
    const float* egam  = (const float*)d_in[5];
    const float* omega = (const float*)d_in[6];
    const float* Wm    = (const float*)d_in[7];
    const float* bm    = (const float*)d_in[8];
    const float* Wz    = (const float*)d_in[9];
    const float* bz    = (const float*)d_in[10];
    const float* Wp    = (const float*)d_in[11];
    const float* bp    = (const float*)d_in[12];
    const float* Whw   = (const float*)d_in[13];
    const float* bhw   = (const float*)d_in[14];
    const float* Whu   = (const float*)d_in[15];
    const float* bhu   = (const float*)d_in[16];
    const float* gamma = (const float*)d_in[17];
    const float* beta  = (const float*)d_in[18];
    const float* rpw   = (const float*)d_in[19];
    float* out = (float*)d_out;

    k_ema_a<<<CH_*B_*E_/256, 256>>>(x, delta, alpha);
    k_ema_b<<<B_*E_/256, 256>>>(delta, alpha);
    k_ema_c<<<CH_*B_*E_/256, 256>>>(x, delta, alpha, ebeta, egam, omega);
    k_mx   <<<dim3(1, 128), 256>>>(Wm, bm);
    k_z    <<<dim3(1, 128), 256>>>(Wz, bz, gamma, beta);
    k_base <<<dim3(40, 128), 256>>>(x, Wp, bp);
    k_S    <<<dim3(16, 16, 8), 256>>>(rpw);
    k_h    <<<dim3(16, 16, 8), 256>>>();
    k_final<<<dim3(8, 128), 256>>>(x, Whw, bhw, Whu, bhu, out);
}

// round 4
// speedup vs baseline: 3.3435x; 1.1969x over previous
#include <cuda_runtime.h>
#include <math.h>
#include <stdint.h>

#define L_  2048
#define B_  8
#define E_  1024
#define Z_  128
#define H_  2048
#define MB_ (L_*B_)   // 16384 rows
#define CH_ 16        // ema chunks
#define CL_ (L_/CH_)  // 128 steps per chunk

// ---------------- scratch (static device allocations; no cudaMalloc) ----------
__device__ float g_ema[MB_*E_];
__device__ float g_mx [MB_*Z_];
__device__ float g_qr [MB_*Z_];
__device__ float g_kr [MB_*Z_];
__device__ float g_u  [MB_*E_];
__device__ float g_r  [MB_*H_];
__device__ float g_v  [MB_*H_];
__device__ float g_S  [B_*L_*L_];
__device__ float g_hr [MB_*H_];
__device__ float g_hend[2*CH_*B_*E_];
__device__ float g_cin [2*CH_*B_*E_];

__device__ __forceinline__ float sigf (float v){ return 1.f/(1.f+expf(-v)); }
__device__ __forceinline__ float siluf(float v){ return v/(1.f+expf(-v)); }

// ---------------- cp.async helpers --------------------------------------------
#define CP_A16(dst_u32, src_ptr) \
    asm volatile("cp.async.ca.shared.global [%0], [%1], 16;\n" :: "r"(dst_u32), "l"(src_ptr) : "memory")
#define CP_COMMIT() asm volatile("cp.async.commit_group;\n" ::: "memory")
#define CP_WAIT(N)  asm volatile("cp.async.wait_group %0;\n" :: "n"(N) : "memory")

// ---------------- tf32 mma core -----------------------------------------------
// block tile 128x128, BK=16, 8 warps (4x2), warp tile 32x64, 2-stage cp.async

struct Stage {
    float A[128][20];
    union { float Bnt[128][20]; float Bnn[16][136]; };
};

__device__ __forceinline__ void mma8(float (&c)[4], const uint32_t (&a)[4], const uint32_t (&b)[2]) {
    asm volatile(
        "mma.sync.aligned.m16n8k8.row.col.f32.tf32.tf32.f32 "
        "{%0,%1,%2,%3},{%4,%5,%6,%7},{%8,%9},{%0,%1,%2,%3};\n"
        : "+f"(c[0]), "+f"(c[1]), "+f"(c[2]), "+f"(c[3])
        : "r"(a[0]), "r"(a[1]), "r"(a[2]), "r"(a[3]), "r"(b[0]), "r"(b[1]));
}

__device__ __forceinline__ void cpa_A(Stage& s, const float* __restrict__ A,
                                      int lda, int m0, int k0, int tid) {
    #pragma unroll
    for (int it = 0; it < 2; it++) {
        int i = tid + 256*it;
        int row = i >> 2, v4 = (i & 3) << 2;
        uint32_t dst = (uint32_t)__cvta_generic_to_shared(&s.A[row][v4]);
        CP_A16(dst, A + (size_t)(m0+row)*lda + k0 + v4);
    }
}
__device__ __forceinline__ void cpa_Bnt(Stage& s, const float* __restrict__ B,
                                        int ldb, int n0, int k0, int tid) {
    #pragma unroll
    for (int it = 0; it < 2; it++) {
        int i = tid + 256*it;
        int row = i >> 2, v4 = (i & 3) << 2;
        uint32_t dst = (uint32_t)__cvta_generic_to_shared(&s.Bnt[row][v4]);
        CP_A16(dst, B + (size_t)(n0+row)*ldb + k0 + v4);
    }
}
__device__ __forceinline__ void cpa_Bnn(Stage& s, const float* __restrict__ B,
                                        int ldb, int n0, int k0, int tid) {
    #pragma unroll
    for (int it = 0; it < 2; it++) {
        int i = tid + 256*it;
        int kk = i >> 5, n4 = (i & 31) << 2;
        uint32_t dst = (uint32_t)__cvta_generic_to_shared(&s.Bnn[kk][n4]);
        CP_A16(dst, B + (size_t)(k0+kk)*ldb + n0 + n4);
    }
}

__device__ __forceinline__ void mma_step_nt(Stage& s, float (&acc)[2][8][4],
                                            int wm, int wn, int g, int t) {
    #pragma unroll
    for (int k8 = 0; k8 < 16; k8 += 8) {
        uint32_t a[2][4];
        #pragma unroll
        for (int mt = 0; mt < 2; mt++) {
            int r = wm + mt*16 + g;
            a[mt][0] = __float_as_uint(s.A[r  ][k8+t  ]);
            a[mt][1] = __float_as_uint(s.A[r+8][k8+t  ]);
            a[mt][2] = __float_as_uint(s.A[r  ][k8+t+4]);
            a[mt][3] = __float_as_uint(s.A[r+8][k8+t+4]);
        }
        #pragma unroll
        for (int nt = 0; nt < 8; nt++) {
            int cN = wn + nt*8 + g;
            uint32_t b[2];
            b[0] = __float_as_uint(s.Bnt[cN][k8+t  ]);
            b[1] = __float_as_uint(s.Bnt[cN][k8+t+4]);
            #pragma unroll
            for (int mt = 0; mt < 2; mt++) mma8(acc[mt][nt], a[mt], b);
        }
    }
}
__device__ __forceinline__ void mma_step_nn(Stage& s, float (&acc)[2][8][4],
                                            int wm, int wn, int g, int t) {
    #pragma unroll
    for (int k8 = 0; k8 < 16; k8 += 8) {
        uint32_t a[2][4];
        #pragma unroll
        for (int mt = 0; mt < 2; mt++) {
            int r = wm + mt*16 + g;
            a[mt][0] = __float_as_uint(s.A[r  ][k8+t  ]);
            a[mt][1] = __float_as_uint(s.A[r+8][k8+t  ]);
            a[mt][2] = __float_as_uint(s.A[r  ][k8+t+4]);
            a[mt][3] = __float_as_uint(s.A[r+8][k8+t+4]);
        }
        #pragma unroll
        for (int nt = 0; nt < 8; nt++) {
            int cN = wn + nt*8 + g;
            uint32_t b[2];
            b[0] = __float_as_uint(s.Bnn[k8+t  ][cN]);
            b[1] = __float_as_uint(s.Bnn[k8+t+4][cN]);
            #pragma unroll
            for (int mt = 0; mt < 2; mt++) mma8(acc[mt][nt], a[mt], b);
        }
    }
}

// C += A(M,K) * B(N,K)^T  — 2-stage pipelined
__device__ __forceinline__ void gemm_nt_mma(const float* __restrict__ A, int lda,
                                            const float* __restrict__ B, int ldb,
                                            int K, int m0, int n0,
                                            Stage (&st)[2], float (&acc)[2][8][4]) {
    const int tid = threadIdx.x;
    const int wid = tid >> 5, lane = tid & 31;
    const int wm = (wid >> 1) * 32, wn = (wid & 1) * 64;
    const int g = lane >> 2, t = lane & 3;
    cpa_A(st[0], A, lda, m0, 0, tid);
    cpa_Bnt(st[0], B, ldb, n0, 0, tid);
    CP_COMMIT();
    for (int k0 = 0; k0 < K; k0 += 16) {
        int cur = (k0 >> 4) & 1;
        bool more = (k0 + 16) < K;
        if (more) {
            cpa_A(st[cur^1], A, lda, m0, k0+16, tid);
            cpa_Bnt(st[cur^1], B, ldb, n0, k0+16, tid);
            CP_COMMIT();
            CP_WAIT(1);
        } else {
            CP_WAIT(0);
        }
        __syncthreads();
        mma_step_nt(st[cur], acc, wm, wn, g, t);
        __syncthreads();
    }
}
// C += A(M,K) * B(K,N)  — 2-stage pipelined
__device__ __forceinline__ void gemm_nn_mma(const float* __restrict__ A, int lda,
                                            const float* __restrict__ B, int ldb,
                                            int K, int m0, int n0,
                                            Stage (&st)[2], float (&acc)[2][8][4]) {
    const int tid = threadIdx.x;
    const int wid = tid >> 5, lane = tid & 31;
    const int wm = (wid >> 1) * 32, wn = (wid & 1) * 64;
    const int g = lane >> 2, t = lane & 3;
    cpa_A(st[0], A, lda, m0, 0, tid);
    cpa_Bnn(st[0], B, ldb, n0, 0, tid);
    CP_COMMIT();
    for (int k0 = 0; k0 < K; k0 += 16) {
        int cur = (k0 >> 4) & 1;
        bool more = (k0 + 16) < K;
        if (more) {
            cpa_A(st[cur^1], A, lda, m0, k0+16, tid);
            cpa_Bnn(st[cur^1], B, ldb, n0, k0+16, tid);
            CP_COMMIT();
            CP_WAIT(1);
        } else {
            CP_WAIT(0);
        }
        __syncthreads();
        mma_step_nn(st[cur], acc, wm, wn, g, t);
        __syncthreads();
    }
}

#define ZERO_ACC4(acc) { _Pragma("unroll") for (int i=0;i<2;i++) _Pragma("unroll") for (int j=0;j<8;j++) _Pragma("unroll") for (int q=0;q<4;q++) acc[i][j][q]=0.f; }

// epilogue pairs: (row, col) with v0=acc[..][2h], v1=acc[..][2h+1]; col even
#define EPI2_BEGIN \
    { const int wid_ = threadIdx.x >> 5, lane_ = threadIdx.x & 31; \
      const int wm_ = (wid_ >> 1)*32, wn_ = (wid_ & 1)*64; \
      const int g_ = lane_ >> 2, t_ = lane_ & 3; \
      _Pragma("unroll") for (int mt = 0; mt < 2; mt++) \
      _Pragma("unroll") for (int nt = 0; nt < 8; nt++) \
      _Pragma("unroll") for (int hq = 0; hq < 2; hq++) { \
          int row = m0 + wm_ + mt*16 + g_ + 8*hq; \
          int col = n0 + wn_ + nt*8 + 2*t_; \
          float v0 = acc[mt][nt][2*hq], v1 = acc[mt][nt][2*hq+1];
#define EPI2_END } }

// ---------------- EMA: 3-phase chunked linear scan ----------------------------
__device__ __forceinline__ void ema_params(int e, const float* delta, const float* alpha,
        float& q0, float& q1) {
    float p0 = sigf(delta[e*2+0]);
    float p1 = sigf(delta[e*2+1]);
    q0 = 1.f - p0*sigf(alpha[e*2+0]);
    q1 = 1.f - p1*sigf(alpha[e*2+1]);
}

__global__ void __launch_bounds__(256) k_ema_a(const float* __restrict__ x,
        const float* __restrict__ delta, const float* __restrict__ alpha)
{
    const int gt = blockIdx.x*256 + threadIdx.x;
    const int be = gt & (B_*E_-1);
    const int c  = gt >> 13;
    const int e  = be & (E_-1);
    float q0, q1; ema_params(e, delta, alpha, q0, q1);
    float h0 = 0.f, h1 = 0.f;
    const float* xp = x + (size_t)(c*CL_)*(B_*E_) + be;
    #pragma unroll 4
    for (int l = 0; l < CL_; l++) {
        float xv = xp[(size_t)l*(B_*E_)];
        h0 = q0*h0 + xv;
        h1 = q1*h1 + xv;
    }
    g_hend[(size_t)c*(B_*E_) + be]       = h0;
    g_hend[(size_t)(CH_+c)*(B_*E_) + be] = h1;
}

__global__ void __launch_bounds__(256) k_ema_b(const float* __restrict__ delta,
        const float* __restrict__ alpha)
{
    const int be = blockIdx.x*256 + threadIdx.x;
    const int e  = be & (E_-1);
    float q0, q1; ema_params(e, delta, alpha, q0, q1);
    float qp0 = q0, qp1 = q1;
    #pragma unroll
    for (int i = 0; i < 7; i++) { qp0 *= qp0; qp1 *= qp1; }   // q^128
    float c0 = 0.f, c1 = 0.f;
    for (int c = 0; c < CH_; c++) {
        g_cin[(size_t)c*(B_*E_) + be]       = c0;
        g_cin[(size_t)(CH_+c)*(B_*E_) + be] = c1;
        c0 = qp0*c0 + g_hend[(size_t)c*(B_*E_) + be];
        c1 = qp1*c1 + g_hend[(size_t)(CH_+c)*(B_*E_) + be];
    }
}

__global__ void __launch_bounds__(256) k_ema_c(const float* __restrict__ x,
        const float* __restrict__ delta, const float* __restrict__ alpha,
        const float* __restrict__ ebeta, const float* __restrict__ egam,
        const float* __restrict__ omega)
{
    const int gt = blockIdx.x*256 + threadIdx.x;
    const int be = gt & (B_*E_-1);
    const int c  = gt >> 13;
    const int e  = be & (E_-1);
    float p0 = sigf(delta[e*2+0]);
    float p1 = sigf(delta[e*2+1]);
    float q0 = 1.f - p0*sigf(alpha[e*2+0]);
    float q1 = 1.f - p1*sigf(alpha[e*2+1]);
    const float sc = 0.70710678118654752f;
    float c0 = p0*ebeta[e*2+0]*egam[e*2+0]*sc;
    float c1 = p1*ebeta[e*2+1]*egam[e*2+1]*sc;
    float om = omega[e];
    float h0 = g_cin[(size_t)c*(B_*E_) + be];
    float h1 = g_cin[(size_t)(CH_+c)*(B_*E_) + be];
    const size_t base = (size_t)(c*CL_)*(B_*E_) + be;
    #pragma unroll 4
    for (int l = 0; l < CL_; l++) {
        float xv = x[base + (size_t)l*(B_*E_)];
        h0 = q0*h0 + xv;
        h1 = q1*h1 + xv;
        float o = c0*h0 + c1*h1 + xv*om;
        g_ema[base + (size_t)l*(B_*E_)] = siluf(o);
    }
}

// ---------------- kernel 2: mx = ema @ Wm^T + bm ------------------------------
__global__ void __launch_bounds__(256) k_mx(const float* __restrict__ Wm,
                                            const float* __restrict__ bm)
{
    __shared__ Stage st[2];
    float acc[2][8][4]; ZERO_ACC4(acc);
    const int m0 = blockIdx.y*128, n0 = blockIdx.x*128;
    gemm_nt_mma(g_ema, E_, Wm, E_, E_, m0, n0, st, acc);
    EPI2_BEGIN
        float2 o = make_float2(v0 + bm[col], v1 + bm[col+1]);
        *(float2*)&g_mx[(size_t)row*Z_ + col] = o;
    EPI2_END
}

// ---------------- kernel 3: z (fp32 FFMA for precision; tiny) -----------------
struct TilesF { float As[16][132]; float Bs[16][132]; };
__global__ void __launch_bounds__(256) k_z(const float* __restrict__ Wz,
        const float* __restrict__ bz, const float* __restrict__ gamma,
        const float* __restrict__ beta)
{
    __shared__ TilesF s;
    float acc[8][8];
    #pragma unroll
    for (int i=0;i<8;i++)
        #pragma unroll
        for (int j=0;j<8;j++) acc[i][j]=0.f;
    const int m0 = blockIdx.y*128;
    const int tid = threadIdx.x;
    const int tm = (tid >> 4) << 3, tn = (tid & 15) << 3;
    for (int k0 = 0; k0 < Z_; k0 += 16) {
        #pragma unroll
        for (int j = 0; j < 8; j++) {
            int i = tid + 256*j;
            int row = i >> 4, kk = i & 15;
            s.As[kk][row] = g_mx[(size_t)(m0+row)*Z_ + k0 + kk];
            s.Bs[kk][row] = Wz[(size_t)row*Z_ + k0 + kk];
        }
        __syncthreads();
        #pragma unroll
        for (int kk = 0; kk < 16; kk++) {
            float a[8], b[8];
            *(float4*)&a[0] = *(const float4*)&s.As[kk][tm];
            *(float4*)&a[4] = *(const float4*)&s.As[kk][tm+4];
            *(float4*)&b[0] = *(const float4*)&s.Bs[kk][tn];
            *(float4*)&b[4] = *(const float4*)&s.Bs[kk][tn+4];
            #pragma unroll
            for (int i = 0; i < 8; i++)
                #pragma unroll
                for (int j = 0; j < 8; j++)
                    acc[i][j] += a[i]*b[j];
        }
        __syncthreads();
    }
    #pragma unroll
    for (int i = 0; i < 8; i++)
        #pragma unroll
        for (int j = 0; j < 8; j++) {
            int m = m0+tm+i, n = tn+j;
            float zz = siluf(acc[i][j] + bz[n]);
            g_qr[(size_t)m*Z_ + n] = zz*gamma[n]    + beta[n];
            g_kr[(size_t)m*Z_ + n] = zz*gamma[Z_+n] + beta[Z_+n];
        }
}

// ---------------- kernel 4: base = x @ Wp^T + bp -> u, r, v ------------------
__global__ void __launch_bounds__(256) k_base(const float* __restrict__ x,
        const float* __restrict__ Wp, const float* __restrict__ bp)
{
    __shared__ Stage st[2];
    float acc[2][8][4]; ZERO_ACC4(acc);
    const int m0 = blockIdx.y*128, n0 = blockIdx.x*128;
    gemm_nt_mma(x, E_, Wp, E_, E_, m0, n0, st, acc);
    EPI2_BEGIN
        float t0 = v0 + bp[col], t1 = v1 + bp[col+1];
        if (col < E_) {
            *(float2*)&g_u[(size_t)row*E_ + col] = make_float2(sigf(t0), sigf(t1));
        } else {
            float2 sv = make_float2(siluf(t0), siluf(t1));
            int n2 = col - E_;
            if (n2 < H_) *(float2*)&g_r[(size_t)row*H_ + n2]      = sv;
            else         *(float2*)&g_v[(size_t)row*H_ + (n2-H_)] = sv;
        }
    EPI2_END
}

// ---------------- kernel 5: S = relu(q k^T / L + bias)^2, causal -------------
__global__ void __launch_bounds__(256) k_S(const float* __restrict__ rpw)
{
    const int b  = blockIdx.z;
    const int m0 = blockIdx.y*128, n0 = blockIdx.x*128;
    if (n0 > m0) return;
    __shared__ Stage st[2];
    float acc[2][8][4]; ZERO_ACC4(acc);
    gemm_nt_mma(g_qr + b*Z_, B_*Z_, g_kr + b*Z_, B_*Z_, Z_, m0, n0, st, acc);
    float* Sb = g_S + (size_t)b*L_*L_;
    const float inv = 1.f / (float)L_;
    EPI2_BEGIN
        float a0 = v0*inv + rpw[(L_-1) + col   - row];
        float a1 = v1*inv + rpw[(L_-1) + col+1 - row];
        a0 = (col   <= row) ? fmaxf(a0, 0.f) : 0.f;
        a1 = (col+1 <= row) ? fmaxf(a1, 0.f) : 0.f;
        *(float2*)&Sb[(size_t)row*L_ + col] = make_float2(a0*a0, a1*a1);
    EPI2_END
}

// ---------------- kernel 6: hr = (S @ v) * r  (causal K truncation) ----------
__global__ void __launch_bounds__(256) k_h()
{
    const int b  = blockIdx.z;
    const int m0 = blockIdx.y*128, n0 = blockIdx.x*128;
    __shared__ Stage st[2];
    float acc[2][8][4]; ZERO_ACC4(acc);
    gemm_nn_mma(g_S + (size_t)b*L_*L_, L_, g_v + b*H_, B_*H_, m0+128, m0, n0, st, acc);
    EPI2_BEGIN
        size_t idx = (size_t)(row*B_ + b)*H_ + col;
        float2 rr = *(const float2*)&g_r[idx];
        *(float2*)&g_hr[idx] = make_float2(v0*rr.x, v1*rr.y);
    EPI2_END
}

// ---------------- kernel 7: out = x + u*(tanh(hr Whw^T + mx Whu^T + b) - x) --
__global__ void __launch_bounds__(256) k_final(const float* __restrict__ x,
        const float* __restrict__ Whw, const float* __restrict__ bhw,
        const float* __restrict__ Whu, const float* __restrict__ bhu,
        float* __restrict__ out)
{
    __shared__ Stage st[2];
    float acc[2][8][4]; ZERO_ACC4(acc);
    const int m0 = blockIdx.y*128, n0 = blockIdx.x*128;
    gemm_nt_mma(g_hr, H_, Whw, H_, H_, m0, n0, st, acc);
    gemm_nt_mma(g_mx, Z_, Whu, Z_, Z_, m0, n0, st, acc);
    EPI2_BEGIN
        float t0 = v0 + bhw[col]   + bhu[col];
        float t1 = v1 + bhw[col+1] + bhu[col+1];
        size_t idx = (size_t)row*E_ + col;
        float2 xv = *(const float2*)&x[idx];
        float2 uu = *(const float2*)&g_u[idx];
        float2 o = make_float2(xv.x + uu.x*(tanhf(t0) - xv.x),
                               xv.y + uu.y*(tanhf(t1) - xv.y));
        *(float2*)&out[idx] = o;
    EPI2_END
}

// -----------------------------------------------------------------------------
extern "C" void kernel_launch(void* const* d_in, const int* in_sizes, int n_in,
                              void* d_out, int out_size)
{
    const float* x     = (const float*)d_in[0];
    const float* delta = (const float*)d_in[2];
    const float* alpha = (const float*)d_in[3];
    const float* ebeta = (const float*)d_in[4];
    const float* egam  = (const float*)d_in[5];
    const float* omega = (const float*)d_in[6];
    const float* Wm    = (const float*)d_in[7];
    const float* bm    = (const float*)d_in[8];
    const float* Wz    = (const float*)d_in[9];
    const float* bz    = (const float*)d_in[10];
    const float* Wp    = (const float*)d_in[11];
    const float* bp    = (const float*)d_in[12];
    const float* Whw   = (const float*)d_in[13];
    const float* bhw   = (const float*)d_in[14];
    const float* Whu   = (const float*)d_in[15];
    const float* bhu   = (const float*)d_in[16];
    const float* gamma = (const float*)d_in[17];
    const float* beta  = (const float*)d_in[18];
    const float* rpw   = (const float*)d_in[19];
    float* out = (float*)d_out;

    k_ema_a<<<CH_*B_*E_/256, 256>>>(x, delta, alpha);
    k_ema_b<<<B_*E_/256, 256>>>(delta, alpha);
    k_ema_c<<<CH_*B_*E_/256, 256>>>(x, delta, alpha, ebeta, egam, omega);
    k_mx   <<<dim3(1, 128), 256>>>(Wm, bm);
    k_z    <<<dim3(1, 128), 256>>>(Wz, bz, gamma, beta);
    k_base <<<dim3(40, 128), 256>>>(x, Wp, bp);
    k_S    <<<dim3(16, 16, 8), 256>>>(rpw);
    k_h    <<<dim3(16, 16, 8), 256>>>();
    k_final<<<dim3(8, 128), 256>>>(x, Whw, bhw, Whu, bhu, out);
}

// round 5
// speedup vs baseline: 3.5242x; 1.0540x over previous
#include <cuda_runtime.h>
#include <math.h>
#include <stdint.h>

#define L_  2048
#define B_  8
#define E_  1024
#define Z_  128
#define H_  2048
#define MB_ (L_*B_)   // 16384 rows
#define CH_ 32        // ema chunks
#define CL_ (L_/CH_)  // 64 steps per chunk

// ---------------- scratch (static device allocations; no cudaMalloc) ----------
__device__ float g_ema[MB_*E_];
__device__ float g_mx [MB_*Z_];
__device__ float g_qr [MB_*Z_];
__device__ float g_kr [MB_*Z_];
__device__ float g_u  [MB_*E_];
__device__ float g_r  [MB_*H_];
__device__ float g_v  [MB_*H_];
__device__ float g_S  [B_*L_*L_];
__device__ float g_hr [MB_*H_];
__device__ float g_hend[2*CH_*B_*E_];
__device__ float g_cin [2*CH_*B_*E_];

__device__ __forceinline__ float sigf (float v){ return 1.f/(1.f+expf(-v)); }
__device__ __forceinline__ float siluf(float v){ return v/(1.f+expf(-v)); }

// ---------------- cp.async helpers --------------------------------------------
#define CP_A16(dst_u32, src_ptr) \
    asm volatile("cp.async.ca.shared.global [%0], [%1], 16;\n" :: "r"(dst_u32), "l"(src_ptr) : "memory")
#define CP_COMMIT() asm volatile("cp.async.commit_group;\n" ::: "memory")
#define CP_WAIT(N)  asm volatile("cp.async.wait_group %0;\n" :: "n"(N) : "memory")

// ---------------- tf32 mma core -----------------------------------------------
// block tile 128x128, BK=16, 4 warps (2x2), warp tile 64x64, 2-stage cp.async,
// single __syncthreads per k-step.

struct Stage {
    float A[128][20];
    union { float Bnt[128][20]; float Bnn[16][136]; };
};

__device__ __forceinline__ void mma8(float (&c)[4], const uint32_t (&a)[4], const uint32_t (&b)[2]) {
    asm volatile(
        "mma.sync.aligned.m16n8k8.row.col.f32.tf32.tf32.f32 "
        "{%0,%1,%2,%3},{%4,%5,%6,%7},{%8,%9},{%0,%1,%2,%3};\n"
        : "+f"(c[0]), "+f"(c[1]), "+f"(c[2]), "+f"(c[3])
        : "r"(a[0]), "r"(a[1]), "r"(a[2]), "r"(a[3]), "r"(b[0]), "r"(b[1]));
}

// 128-thread loaders: 512 16B-chunks per 128x16 tile -> 4 per thread
__device__ __forceinline__ void cpa_A(Stage& s, const float* __restrict__ A,
                                      int lda, int m0, int k0, int tid) {
    #pragma unroll
    for (int it = 0; it < 4; it++) {
        int i = tid + 128*it;
        int row = i >> 2, v4 = (i & 3) << 2;
        uint32_t dst = (uint32_t)__cvta_generic_to_shared(&s.A[row][v4]);
        CP_A16(dst, A + (size_t)(m0+row)*lda + k0 + v4);
    }
}
__device__ __forceinline__ void cpa_Bnt(Stage& s, const float* __restrict__ B,
                                        int ldb, int n0, int k0, int tid) {
    #pragma unroll
    for (int it = 0; it < 4; it++) {
        int i = tid + 128*it;
        int row = i >> 2, v4 = (i & 3) << 2;
        uint32_t dst = (uint32_t)__cvta_generic_to_shared(&s.Bnt[row][v4]);
        CP_A16(dst, B + (size_t)(n0+row)*ldb + k0 + v4);
    }
}
__device__ __forceinline__ void cpa_Bnn(Stage& s, const float* __restrict__ B,
                                        int ldb, int n0, int k0, int tid) {
    #pragma unroll
    for (int it = 0; it < 4; it++) {
        int i = tid + 128*it;
        int kk = i >> 5, n4 = (i & 31) << 2;
        uint32_t dst = (uint32_t)__cvta_generic_to_shared(&s.Bnn[kk][n4]);
        CP_A16(dst, B + (size_t)(k0+kk)*ldb + n0 + n4);
    }
}

__device__ __forceinline__ void mma_step_nt(Stage& s, float (&acc)[4][8][4],
                                            int wm, int wn, int g, int t) {
    #pragma unroll
    for (int k8 = 0; k8 < 16; k8 += 8) {
        uint32_t a[4][4];
        #pragma unroll
        for (int mt = 0; mt < 4; mt++) {
            int r = wm + mt*16 + g;
            a[mt][0] = __float_as_uint(s.A[r  ][k8+t  ]);
            a[mt][1] = __float_as_uint(s.A[r+8][k8+t  ]);
            a[mt][2] = __float_as_uint(s.A[r  ][k8+t+4]);
            a[mt][3] = __float_as_uint(s.A[r+8][k8+t+4]);
        }
        #pragma unroll
        for (int nt = 0; nt < 8; nt++) {
            int cN = wn + nt*8 + g;
            uint32_t b[2];
            b[0] = __float_as_uint(s.Bnt[cN][k8+t  ]);
            b[1] = __float_as_uint(s.Bnt[cN][k8+t+4]);
            #pragma unroll
            for (int mt = 0; mt < 4; mt++) mma8(acc[mt][nt], a[mt], b);
        }
    }
}
__device__ __forceinline__ void mma_step_nn(Stage& s, float (&acc)[4][8][4],
                                            int wm, int wn, int g, int t) {
    #pragma unroll
    for (int k8 = 0; k8 < 16; k8 += 8) {
        uint32_t a[4][4];
        #pragma unroll
        for (int mt = 0; mt < 4; mt++) {
            int r = wm + mt*16 + g;
            a[mt][0] = __float_as_uint(s.A[r  ][k8+t  ]);
            a[mt][1] = __float_as_uint(s.A[r+8][k8+t  ]);
            a[mt][2] = __float_as_uint(s.A[r  ][k8+t+4]);
            a[mt][3] = __float_as_uint(s.A[r+8][k8+t+4]);
        }
        #pragma unroll
        for (int nt = 0; nt < 8; nt++) {
            int cN = wn + nt*8 + g;
            uint32_t b[2];
            b[0] = __float_as_uint(s.Bnn[k8+t  ][cN]);
            b[1] = __float_as_uint(s.Bnn[k8+t+4][cN]);
            #pragma unroll
            for (int mt = 0; mt < 4; mt++) mma8(acc[mt][nt], a[mt], b);
        }
    }
}

// C += A(M,K) * B(N,K)^T  — 2-stage, one sync per k-step
__device__ __forceinline__ void gemm_nt_mma(const float* __restrict__ A, int lda,
                                            const float* __restrict__ B, int ldb,
                                            int K, int m0, int n0,
                                            Stage (&st)[2], float (&acc)[4][8][4]) {
    const int tid = threadIdx.x;
    const int wid = tid >> 5, lane = tid & 31;
    const int wm = (wid >> 1) * 64, wn = (wid & 1) * 64;
    const int g = lane >> 2, t = lane & 3;
    cpa_A(st[0], A, lda, m0, 0, tid);
    cpa_Bnt(st[0], B, ldb, n0, 0, tid);
    CP_COMMIT();
    const int nk = K >> 4;
    for (int i = 0; i < nk; i++) {
        int cur = i & 1;
        CP_WAIT(0);
        __syncthreads();          // tile i visible; all warps done with buf cur^1
        if (i + 1 < nk) {
            cpa_A(st[cur^1], A, lda, m0, (i+1)<<4, tid);
            cpa_Bnt(st[cur^1], B, ldb, n0, (i+1)<<4, tid);
            CP_COMMIT();
        }
        mma_step_nt(st[cur], acc, wm, wn, g, t);
    }
    __syncthreads();              // protect stage reuse by a following gemm call
}
// C += A(M,K) * B(K,N)
__device__ __forceinline__ void gemm_nn_mma(const float* __restrict__ A, int lda,
                                            const float* __restrict__ B, int ldb,
                                            int K, int m0, int n0,
                                            Stage (&st)[2], float (&acc)[4][8][4]) {
    const int tid = threadIdx.x;
    const int wid = tid >> 5, lane = tid & 31;
    const int wm = (wid >> 1) * 64, wn = (wid & 1) * 64;
    const int g = lane >> 2, t = lane & 3;
    cpa_A(st[0], A, lda, m0, 0, tid);
    cpa_Bnn(st[0], B, ldb, n0, 0, tid);
    CP_COMMIT();
    const int nk = K >> 4;
    for (int i = 0; i < nk; i++) {
        int cur = i & 1;
        CP_WAIT(0);
        __syncthreads();
        if (i + 1 < nk) {
            cpa_A(st[cur^1], A, lda, m0, (i+1)<<4, tid);
            cpa_Bnn(st[cur^1], B, ldb, n0, (i+1)<<4, tid);
            CP_COMMIT();
        }
        mma_step_nn(st[cur], acc, wm, wn, g, t);
    }
    __syncthreads();
}

#define ZERO_ACC4(acc) { _Pragma("unroll") for (int i=0;i<4;i++) _Pragma("unroll") for (int j=0;j<8;j++) _Pragma("unroll") for (int q=0;q<4;q++) acc[i][j][q]=0.f; }

// epilogue pairs: (row, col) with v0, v1 at columns col, col+1 (col even)
#define EPI2_BEGIN \
    { const int wid_ = threadIdx.x >> 5, lane_ = threadIdx.x & 31; \
      const int wm_ = (wid_ >> 1)*64, wn_ = (wid_ & 1)*64; \
      const int g_ = lane_ >> 2, t_ = lane_ & 3; \
      _Pragma("unroll") for (int mt = 0; mt < 4; mt++) \
      _Pragma("unroll") for (int nt = 0; nt < 8; nt++) \
      _Pragma("unroll") for (int hq = 0; hq < 2; hq++) { \
          int row = m0 + wm_ + mt*16 + g_ + 8*hq; \
          int col = n0 + wn_ + nt*8 + 2*t_; \
          float v0 = acc[mt][nt][2*hq], v1 = acc[mt][nt][2*hq+1];
#define EPI2_END } }

// ---------------- EMA: 3-phase chunked linear scan ----------------------------
__device__ __forceinline__ void ema_params(int e, const float* delta, const float* alpha,
        float& q0, float& q1) {
    float p0 = sigf(delta[e*2+0]);
    float p1 = sigf(delta[e*2+1]);
    q0 = 1.f - p0*sigf(alpha[e*2+0]);
    q1 = 1.f - p1*sigf(alpha[e*2+1]);
}

__global__ void __launch_bounds__(256) k_ema_a(const float* __restrict__ x,
        const float* __restrict__ delta, const float* __restrict__ alpha)
{
    const int gt = blockIdx.x*256 + threadIdx.x;
    const int be = gt & (B_*E_-1);
    const int c  = gt >> 13;
    const int e  = be & (E_-1);
    float q0, q1; ema_params(e, delta, alpha, q0, q1);
    float h0 = 0.f, h1 = 0.f;
    const float* xp = x + (size_t)(c*CL_)*(B_*E_) + be;
    #pragma unroll 4
    for (int l = 0; l < CL_; l++) {
        float xv = xp[(size_t)l*(B_*E_)];
        h0 = q0*h0 + xv;
        h1 = q1*h1 + xv;
    }
    g_hend[(size_t)c*(B_*E_) + be]       = h0;
    g_hend[(size_t)(CH_+c)*(B_*E_) + be] = h1;
}

__global__ void __launch_bounds__(256) k_ema_b(const float* __restrict__ delta,
        const float* __restrict__ alpha)
{
    const int be = blockIdx.x*256 + threadIdx.x;
    const int e  = be & (E_-1);
    float q0, q1; ema_params(e, delta, alpha, q0, q1);
    float qp0 = q0, qp1 = q1;
    #pragma unroll
    for (int i = 0; i < 6; i++) { qp0 *= qp0; qp1 *= qp1; }   // q^64 (CL_=64)
    float c0 = 0.f, c1 = 0.f;
    for (int c = 0; c < CH_; c++) {
        g_cin[(size_t)c*(B_*E_) + be]       = c0;
        g_cin[(size_t)(CH_+c)*(B_*E_) + be] = c1;
        c0 = qp0*c0 + g_hend[(size_t)c*(B_*E_) + be];
        c1 = qp1*c1 + g_hend[(size_t)(CH_+c)*(B_*E_) + be];
    }
}

__global__ void __launch_bounds__(256) k_ema_c(const float* __restrict__ x,
        const float* __restrict__ delta, const float* __restrict__ alpha,
        const float* __restrict__ ebeta, const float* __restrict__ egam,
        const float* __restrict__ omega)
{
    const int gt = blockIdx.x*256 + threadIdx.x;
    const int be = gt & (B_*E_-1);
    const int c  = gt >> 13;
    const int e  = be & (E_-1);
    float p0 = sigf(delta[e*2+0]);
    float p1 = sigf(delta[e*2+1]);
    float q0 = 1.f - p0*sigf(alpha[e*2+0]);
    float q1 = 1.f - p1*sigf(alpha[e*2+1]);
    const float sc = 0.70710678118654752f;
    float c0 = p0*ebeta[e*2+0]*egam[e*2+0]*sc;
    float c1 = p1*ebeta[e*2+1]*egam[e*2+1]*sc;
    float om = omega[e];
    float h0 = g_cin[(size_t)c*(B_*E_) + be];
    float h1 = g_cin[(size_t)(CH_+c)*(B_*E_) + be];
    const size_t base = (size_t)(c*CL_)*(B_*E_) + be;
    #pragma unroll 4
    for (int l = 0; l < CL_; l++) {
        float xv = x[base + (size_t)l*(B_*E_)];
        h0 = q0*h0 + xv;
        h1 = q1*h1 + xv;
        float o = c0*h0 + c1*h1 + xv*om;
        g_ema[base + (size_t)l*(B_*E_)] = siluf(o);
    }
}

// ---------------- kernel 2: mx = ema @ Wm^T + bm ------------------------------
__global__ void __launch_bounds__(128) k_mx(const float* __restrict__ Wm,
                                            const float* __restrict__ bm)
{
    __shared__ Stage st[2];
    float acc[4][8][4]; ZERO_ACC4(acc);
    const int m0 = blockIdx.y*128, n0 = blockIdx.x*128;
    gemm_nt_mma(g_ema, E_, Wm, E_, E_, m0, n0, st, acc);
    EPI2_BEGIN
        float2 o = make_float2(v0 + bm[col], v1 + bm[col+1]);
        *(float2*)&g_mx[(size_t)row*Z_ + col] = o;
    EPI2_END
}

// ---------------- kernel 3: z (fp32 FFMA for precision; tiny) -----------------
struct TilesF { float As[16][132]; float Bs[16][132]; };
__global__ void __launch_bounds__(256) k_z(const float* __restrict__ Wz,
        const float* __restrict__ bz, const float* __restrict__ gamma,
        const float* __restrict__ beta)
{
    __shared__ TilesF s;
    float acc[8][8];
    #pragma unroll
    for (int i=0;i<8;i++)
        #pragma unroll
        for (int j=0;j<8;j++) acc[i][j]=0.f;
    const int m0 = blockIdx.y*128;
    const int tid = threadIdx.x;
    const int tm = (tid >> 4) << 3, tn = (tid & 15) << 3;
    for (int k0 = 0; k0 < Z_; k0 += 16) {
        #pragma unroll
        for (int j = 0; j < 8; j++) {
            int i = tid + 256*j;
            int row = i >> 4, kk = i & 15;
            s.As[kk][row] = g_mx[(size_t)(m0+row)*Z_ + k0 + kk];
            s.Bs[kk][row] = Wz[(size_t)row*Z_ + k0 + kk];
        }
        __syncthreads();
        #pragma unroll
        for (int kk = 0; kk < 16; kk++) {
            float a[8], b[8];
            *(float4*)&a[0] = *(const float4*)&s.As[kk][tm];
            *(float4*)&a[4] = *(const float4*)&s.As[kk][tm+4];
            *(float4*)&b[0] = *(const float4*)&s.Bs[kk][tn];
            *(float4*)&b[4] = *(const float4*)&s.Bs[kk][tn+4];
            #pragma unroll
            for (int i = 0; i < 8; i++)
                #pragma unroll
                for (int j = 0; j < 8; j++)
                    acc[i][j] += a[i]*b[j];
        }
        __syncthreads();
    }
    #pragma unroll
    for (int i = 0; i < 8; i++)
        #pragma unroll
        for (int j = 0; j < 8; j++) {
            int m = m0+tm+i, n = tn+j;
            float zz = siluf(acc[i][j] + bz[n]);
            g_qr[(size_t)m*Z_ + n] = zz*gamma[n]    + beta[n];
            g_kr[(size_t)m*Z_ + n] = zz*gamma[Z_+n] + beta[Z_+n];
        }
}

// ---------------- kernel 4: base = x @ Wp^T + bp -> u, r, v ------------------
__global__ void __launch_bounds__(128) k_base(const float* __restrict__ x,
        const float* __restrict__ Wp, const float* __restrict__ bp)
{
    __shared__ Stage st[2];
    float acc[4][8][4]; ZERO_ACC4(acc);
    const int m0 = blockIdx.y*128, n0 = blockIdx.x*128;
    gemm_nt_mma(x, E_, Wp, E_, E_, m0, n0, st, acc);
    EPI2_BEGIN
        float t0 = v0 + bp[col], t1 = v1 + bp[col+1];
        if (col < E_) {
            *(float2*)&g_u[(size_t)row*E_ + col] = make_float2(sigf(t0), sigf(t1));
        } else {
            float2 sv = make_float2(siluf(t0), siluf(t1));
            int n2 = col - E_;
            if (n2 < H_) *(float2*)&g_r[(size_t)row*H_ + n2]      = sv;
            else         *(float2*)&g_v[(size_t)row*H_ + (n2-H_)] = sv;
        }
    EPI2_END
}

// ---------------- kernel 5: S = relu(q k^T / L + bias)^2, causal -------------
__global__ void __launch_bounds__(128) k_S(const float* __restrict__ rpw)
{
    const int b  = blockIdx.z;
    const int m0 = blockIdx.y*128, n0 = blockIdx.x*128;
    if (n0 > m0) return;
    __shared__ Stage st[2];
    float acc[4][8][4]; ZERO_ACC4(acc);
    gemm_nt_mma(g_qr + b*Z_, B_*Z_, g_kr + b*Z_, B_*Z_, Z_, m0, n0, st, acc);
    float* Sb = g_S + (size_t)b*L_*L_;
    const float inv = 1.f / (float)L_;
    EPI2_BEGIN
        float a0 = v0*inv + rpw[(L_-1) + col   - row];
        float a1 = v1*inv + rpw[(L_-1) + col+1 - row];
        a0 = (col   <= row) ? fmaxf(a0, 0.f) : 0.f;
        a1 = (col+1 <= row) ? fmaxf(a1, 0.f) : 0.f;
        *(float2*)&Sb[(size_t)row*L_ + col] = make_float2(a0*a0, a1*a1);
    EPI2_END
}

// ---------------- kernel 6: hr = (S @ v) * r  (causal K truncation) ----------
__global__ void __launch_bounds__(128) k_h()
{
    const int b  = blockIdx.z;
    const int m0 = blockIdx.y*128, n0 = blockIdx.x*128;
    __shared__ Stage st[2];
    float acc[4][8][4]; ZERO_ACC4(acc);
    gemm_nn_mma(g_S + (size_t)b*L_*L_, L_, g_v + b*H_, B_*H_, m0+128, m0, n0, st, acc);
    EPI2_BEGIN
        size_t idx = (size_t)(row*B_ + b)*H_ + col;
        float2 rr = *(const float2*)&g_r[idx];
        *(float2*)&g_hr[idx] = make_float2(v0*rr.x, v1*rr.y);
    EPI2_END
}

// ---------------- kernel 7: out = x + u*(tanh(hr Whw^T + mx Whu^T + b) - x) --
__global__ void __launch_bounds__(128) k_final(const float* __restrict__ x,
        const float* __restrict__ Whw, const float* __restrict__ bhw,
        const float* __restrict__ Whu, const float* __restrict__ bhu,
        float* __restrict__ out)
{
    __shared__ Stage st[2];
    float acc[4][8][4]; ZERO_ACC4(acc);
    const int m0 = blockIdx.y*128, n0 = blockIdx.x*128;
    gemm_nt_mma(g_hr, H_, Whw, H_, H_, m0, n0, st, acc);
    gemm_nt_mma(g_mx, Z_, Whu, Z_, Z_, m0, n0, st, acc);
    EPI2_BEGIN
        float t0 = v0 + bhw[col]   + bhu[col];
        float t1 = v1 + bhw[col+1] + bhu[col+1];
        size_t idx = (size_t)row*E_ + col;
        float2 xv = *(const float2*)&x[idx];
        float2 uu = *(const float2*)&g_u[idx];
        float2 o = make_float2(xv.x + uu.x*(tanhf(t0) - xv.x),
                               xv.y + uu.y*(tanhf(t1) - xv.y));
        *(float2*)&out[idx] = o;
    EPI2_END
}

// -----------------------------------------------------------------------------
extern "C" void kernel_launch(void* const* d_in, const int* in_sizes, int n_in,
                              void* d_out, int out_size)
{
    const float* x     = (const float*)d_in[0];
    const float* delta = (const float*)d_in[2];
    const float* alpha = (const float*)d_in[3];
    const float* ebeta = (const float*)d_in[4];
    const float* egam  = (const float*)d_in[5];
    const float* omega = (const float*)d_in[6];
    const float* Wm    = (const float*)d_in[7];
    const float* bm    = (const float*)d_in[8];
    const float* Wz    = (const float*)d_in[9];
    const float* bz    = (const float*)d_in[10];
    const float* Wp    = (const float*)d_in[11];
    const float* bp    = (const float*)d_in[12];
    const float* Whw   = (const float*)d_in[13];
    const float* bhw   = (const float*)d_in[14];
    const float* Whu   = (const float*)d_in[15];
    const float* bhu   = (const float*)d_in[16];
    const float* gamma = (const float*)d_in[17];
    const float* beta  = (const float*)d_in[18];
    const float* rpw   = (const float*)d_in[19];
    float* out = (float*)d_out;

    k_ema_a<<<CH_*B_*E_/256, 256>>>(x, delta, alpha);
    k_ema_b<<<B_*E_/256, 256>>>(delta, alpha);
    k_ema_c<<<CH_*B_*E_/256, 256>>>(x, delta, alpha, ebeta, egam, omega);
    k_mx   <<<dim3(1, 128), 128>>>(Wm, bm);
    k_z    <<<dim3(1, 128), 256>>>(Wz, bz, gamma, beta);
    k_base <<<dim3(40, 128), 128>>>(x, Wp, bp);
    k_S    <<<dim3(16, 16, 8), 128>>>(rpw);
    k_h    <<<dim3(16, 16, 8), 128>>>();
    k_final<<<dim3(8, 128), 128>>>(x, Whw, bhw, Whu, bhu, out);
}